// round 9
// baseline (speedup 1.0000x reference)
#include <cuda_runtime.h>
#include <math.h>

// Problem constants
#define BB 256    // batch
#define LL 32     // seq len
#define DD 512    // input dim
#define HH 512    // hidden
#define NN 63     // max nodes per batch
#define PP 2560   // 5*H projection width

// ---------------------------------------------------------------------------
// Persistent device state (deterministically rewritten each replay; stale
// values are provably never consulted for the output).
// ---------------------------------------------------------------------------
__device__ float g_h [BB][NN][HH];
__device__ float g_c [BB][NN][HH];
__device__ float g_pl[BB][NN][PP];
__device__ float g_pr[BB][NN][PP];
__device__ float g_ch[BB][NN][HH];
__device__ float g_cc[BB][NN][HH];
__device__ float g_lg[BB][NN];
__device__ int   g_seq[BB][LL];
__device__ int   g_new[BB];
__device__ int   g_rec[BB][2][2];
__device__ int   g_recn[BB];
__device__ int   g_perm[BB];
__device__ int   g_slen[BB];
__device__ int   g_cntge[34];
__device__ int   g_off[33];
__device__ int   g_nrows;
__device__ int   g_rowmap[BB * LL];

__device__ __forceinline__ float sigmoidf_(float x) {
    return 1.0f / (1.0f + expf(-x));
}

// ---------------------------------------------------------------------------
// Sort batches by length descending (stable) + prefix counts + compacted
// (leaf,slot) row list. One block.
// ---------------------------------------------------------------------------
__global__ void k_sort(const int* __restrict__ length) {
    int tid = threadIdx.x;
    if (tid == 0) {
        int cnt[33];
        for (int v = 0; v < 33; v++) cnt[v] = 0;
        for (int b = 0; b < BB; b++) cnt[length[b]]++;
        int pos[33];
        int acc = 0;
        for (int v = 32; v >= 0; v--) { pos[v] = acc; acc += cnt[v]; }
        for (int b = 0; b < BB; b++) {
            int v = length[b];
            int sl = pos[v]++;
            g_perm[sl] = b;
            g_slen[sl] = v;
        }
        for (int t = 0; t < 34; t++) {
            int c = 0;
            for (int v = t; v < 33; v++) c += cnt[v];
            g_cntge[t] = c;
        }
        int off = 0;
        for (int l = 0; l < 32; l++) { g_off[l] = off; off += g_cntge[l + 1]; }
        g_off[32] = off;
        g_nrows = off;
    }
    __syncthreads();
    for (int l = 0; l < 32; l++)
        if (tid < g_cntge[l + 1])
            g_rowmap[g_off[l] + tid] = (l << 8) | tid;
}

// ---------------------------------------------------------------------------
// Big fp32 GEMM over COMPACTED rows: 128x128 tile, BK=8, 256 threads, 8x8.
// (unchanged — measured ~44 TF/s)
// ---------------------------------------------------------------------------
__global__ void __launch_bounds__(256)
k_gemm_big(int mode, const float* __restrict__ X, const float* __restrict__ W,
           const float* __restrict__ bias) {
    __shared__ float As[8][132];
    __shared__ float Bs[8][132];
    int bm = blockIdx.y * 128;
    int nrows = g_nrows;
    if (bm >= nrows) return;
    int bn = blockIdx.x * 128;

    int tid = threadIdx.x;
    int lr = tid >> 1;          // 0..127 load row
    int lc = (tid & 1) << 2;    // 0 or 4

    int r = bm + lr;
    int rm = g_rowmap[(r < nrows) ? r : bm];
    int l = rm >> 8, s = rm & 255;
    const float* arow;
    if (mode == 0) arow = X + ((long)g_perm[s] * LL + l) * DD + lc;
    else           arow = &g_h[s][l][lc];

    int nrow = bn + lr;
    const float* brow;
    if (mode == 0) brow = W + (long)nrow * DD + lc;
    else brow = (nrow < PP) ? (W + (long)nrow * (2 * HH) + lc)
                            : (W + (long)(nrow - PP) * (2 * HH) + HH + lc);

    int tx = tid & 15, ty = tid >> 4;
    float acc[8][8];
#pragma unroll
    for (int i = 0; i < 8; i++)
#pragma unroll
        for (int j = 0; j < 8; j++) acc[i][j] = 0.0f;

    for (int k0 = 0; k0 < DD; k0 += 8) {
        float4 a = *(const float4*)(arow + k0);
        float4 b = *(const float4*)(brow + k0);
        As[lc + 0][lr] = a.x; As[lc + 1][lr] = a.y;
        As[lc + 2][lr] = a.z; As[lc + 3][lr] = a.w;
        Bs[lc + 0][lr] = b.x; Bs[lc + 1][lr] = b.y;
        Bs[lc + 2][lr] = b.z; Bs[lc + 3][lr] = b.w;
        __syncthreads();
#pragma unroll
        for (int k = 0; k < 8; k++) {
            float av[8], bv[8];
            float4 t0 = *(const float4*)&As[k][ty * 4];
            float4 t1 = *(const float4*)&As[k][64 + ty * 4];
            av[0]=t0.x; av[1]=t0.y; av[2]=t0.z; av[3]=t0.w;
            av[4]=t1.x; av[5]=t1.y; av[6]=t1.z; av[7]=t1.w;
            float4 u0 = *(const float4*)&Bs[k][tx * 4];
            float4 u1 = *(const float4*)&Bs[k][64 + tx * 4];
            bv[0]=u0.x; bv[1]=u0.y; bv[2]=u0.z; bv[3]=u0.w;
            bv[4]=u1.x; bv[5]=u1.y; bv[6]=u1.z; bv[7]=u1.w;
#pragma unroll
            for (int i = 0; i < 8; i++)
#pragma unroll
                for (int j = 0; j < 8; j++)
                    acc[i][j] = fmaf(av[i], bv[j], acc[i][j]);
        }
        __syncthreads();
    }

#pragma unroll
    for (int i = 0; i < 8; i++) {
        int mi = (i < 4) ? (ty * 4 + i) : (64 + ty * 4 + (i - 4));
        int r2 = bm + mi;
        if (r2 >= nrows) continue;
        int rm2 = g_rowmap[r2];
        int l2 = rm2 >> 8, s2 = rm2 & 255;
#pragma unroll
        for (int j = 0; j < 8; j++) {
            int nj = (j < 4) ? (tx * 4 + j) : (64 + tx * 4 + (j - 4));
            int n = bn + nj;
            float v = acc[i][j];
            if (mode == 0) {
                v += bias[n];
                if (n < HH) g_h[s2][l2][n] = v;
                else        g_c[s2][l2][n - HH] = v;
            } else {
                if (n < PP) g_pl[s2][l2][n] = v;
                else        g_pr[s2][l2][n - PP] = v;
            }
        }
    }
}

// ---------------------------------------------------------------------------
// Per-iteration node-projection GEMM v3: 64x64 tile, 128 threads (4 warps),
// 4x8 microtile (32 FFMA : 3 LDS.128 per k), BK=16, register prefetch,
// conflict-free smem stores, float4 epilogue. Grid (80, 4) = 320 CTAs.
// Rows needing the new node's projection: s < cntge[iter+3].
// Accumulation order per output unchanged -> bit-identical results.
// ---------------------------------------------------------------------------
__global__ void __launch_bounds__(128)
k_gemm_nodes(int iter, const float* __restrict__ W) {
    __shared__ float As[16][68];
    __shared__ float Bs[16][68];
    int act = g_cntge[iter + 3];
    int bm = blockIdx.y * 64;
    if (bm >= act) return;
    int bn = blockIdx.x * 64;
    int t = threadIdx.x;

    // loaders: 64 rows x 16 K = 1024 floats each for A and B;
    // 128 threads x 2 float4. Warps 0-1 load K[0:8), warps 2-3 K[8:16).
    int lr = t & 63;            // row 0..63
    int lc = (t >> 6) << 3;     // K offset 0 or 8

    int s = bm + lr;
    int sc = (s < act) ? s : bm;
    const float* arow = &g_h[sc][g_new[sc]][lc];
    int nrow = bn + lr;
    const float* brow = ((nrow < PP) ? (W + (long)nrow * (2 * HH))
                                     : (W + (long)(nrow - PP) * (2 * HH) + HH)) + lc;

    int tx = t & 7, ty = t >> 3;   // tx: 8 N-groups of 8; ty: 16 M-groups of 4
    float acc[4][8];
#pragma unroll
    for (int i = 0; i < 4; i++)
#pragma unroll
        for (int j = 0; j < 8; j++) acc[i][j] = 0.0f;

    float4 pa0 = *(const float4*)arow;
    float4 pa1 = *(const float4*)(arow + 4);
    float4 pb0 = *(const float4*)brow;
    float4 pb1 = *(const float4*)(brow + 4);

    for (int k0 = 0; k0 < DD; k0 += 16) {
        As[lc + 0][lr] = pa0.x; As[lc + 1][lr] = pa0.y;
        As[lc + 2][lr] = pa0.z; As[lc + 3][lr] = pa0.w;
        As[lc + 4][lr] = pa1.x; As[lc + 5][lr] = pa1.y;
        As[lc + 6][lr] = pa1.z; As[lc + 7][lr] = pa1.w;
        Bs[lc + 0][lr] = pb0.x; Bs[lc + 1][lr] = pb0.y;
        Bs[lc + 2][lr] = pb0.z; Bs[lc + 3][lr] = pb0.w;
        Bs[lc + 4][lr] = pb1.x; Bs[lc + 5][lr] = pb1.y;
        Bs[lc + 6][lr] = pb1.z; Bs[lc + 7][lr] = pb1.w;
        __syncthreads();
        if (k0 + 16 < DD) {
            pa0 = *(const float4*)(arow + k0 + 16);
            pa1 = *(const float4*)(arow + k0 + 20);
            pb0 = *(const float4*)(brow + k0 + 16);
            pb1 = *(const float4*)(brow + k0 + 20);
        }
#pragma unroll
        for (int k = 0; k < 16; k++) {
            float4 av = *(const float4*)&As[k][ty * 4];       // 8-way bcast
            float4 b0 = *(const float4*)&Bs[k][tx * 8];       // 4-way bcast
            float4 b1 = *(const float4*)&Bs[k][tx * 8 + 4];
            float ar[4] = {av.x, av.y, av.z, av.w};
            float br[8] = {b0.x, b0.y, b0.z, b0.w, b1.x, b1.y, b1.z, b1.w};
#pragma unroll
            for (int i = 0; i < 4; i++)
#pragma unroll
                for (int j = 0; j < 8; j++)
                    acc[i][j] = fmaf(ar[i], br[j], acc[i][j]);
        }
        __syncthreads();
    }

    // Whole 64-wide N-tile is uniformly pl or pr (PP % 64 == 0).
    int nb = bn + tx * 8;
#pragma unroll
    for (int i = 0; i < 4; i++) {
        int ss = bm + ty * 4 + i;
        if (ss >= act) continue;
        int node = g_new[ss];
        float* dst = (bn < PP) ? &g_pl[ss][node][nb] : &g_pr[ss][node][nb - PP];
        *(float4*)dst       = make_float4(acc[i][0], acc[i][1], acc[i][2], acc[i][3]);
        *(float4*)(dst + 4) = make_float4(acc[i][4], acc[i][5], acc[i][6], acc[i][7]);
    }
}

// ---------------------------------------------------------------------------
// Iteration-0 candidate compose for all initial pairs. Grid (31, 256).
// ---------------------------------------------------------------------------
__global__ void __launch_bounds__(512)
k_cand(const float* __restrict__ bcomp, const float* __restrict__ q) {
    int s = blockIdx.y;
    int slot = blockIdx.x;
    if (slot >= g_slen[s] - 1) return;
    int left = slot, right = slot + 1;
    int k = threadIdx.x;
    const float* pl = g_pl[s][left];
    const float* pr = g_pr[s][right];
    float vi  = pl[k]        + pr[k]        + bcomp[k];
    float vfl = pl[k + 512]  + pr[k + 512]  + bcomp[k + 512];
    float vfr = pl[k + 1024] + pr[k + 1024] + bcomp[k + 1024];
    float vu  = pl[k + 1536] + pr[k + 1536] + bcomp[k + 1536];
    float vo  = pl[k + 2048] + pr[k + 2048] + bcomp[k + 2048];
    float cl = g_c[s][left][k];
    float cr = g_c[s][right][k];
    float cc = cl * sigmoidf_(vfl + 1.0f) + cr * sigmoidf_(vfr + 1.0f)
             + tanhf(vu) * sigmoidf_(vi);
    float hh = sigmoidf_(vo) * tanhf(cc);
    g_ch[s][left][k] = hh;
    g_cc[s][left][k] = cc;

    float part = q[k] * hh;
#pragma unroll
    for (int o = 16; o > 0; o >>= 1)
        part += __shfl_down_sync(0xffffffffu, part, o);
    __shared__ float red[16];
    if ((k & 31) == 0) red[k >> 5] = part;
    __syncthreads();
    if (k < 16) {
        float v = red[k];
#pragma unroll
        for (int o = 8; o > 0; o >>= 1)
            v += __shfl_down_sync(0xffffu, v, o);
        if (k == 0) g_lg[s][left] = v * 0.04419417382415922f;  // 1/sqrt(512)
    }
}

// ---------------------------------------------------------------------------
// Iteration-0 merge (argmax + install + shift). One block per slot.
// ---------------------------------------------------------------------------
__global__ void __launch_bounds__(512)
k_merge0() {
    int s = blockIdx.x;
    int t = threadIdx.x;
    int len = g_slen[s];
    int valid = len - 1;
    __shared__ int seq[LL];
    __shared__ int sh_bm;
    if (t < LL) seq[t] = t;
    __syncthreads();
    if (t == 0) {
        float best = -3.4e38f;
        int bm = 0;
        for (int j = 0; j < valid; j++) {
            float lg = g_lg[s][seq[j]];
            if (lg > best) { best = lg; bm = j; }
        }
        sh_bm = bm;
        int newid = LL;
        int c = 0;
        if (bm > 0)       { g_rec[s][c][0] = seq[bm - 1]; g_rec[s][c][1] = newid;       c++; }
        if (bm + 2 < len) { g_rec[s][c][0] = newid;       g_rec[s][c][1] = seq[bm + 2]; c++; }
        g_recn[s] = c;
        g_new[s] = newid;
    }
    __syncthreads();
    int bm = sh_bm;
    int leftid = seq[bm];
    int newid = LL;
    g_h[s][newid][t] = g_ch[s][leftid][t];
    g_c[s][newid][t] = g_cc[s][leftid][t];
    if (t < LL - 1)
        g_seq[s][t] = (t < bm) ? seq[t] : ((t == bm) ? newid : seq[t + 1]);
}

// ---------------------------------------------------------------------------
// Fused per-iteration step (iter >= 1): recompute <=2 candidate pairs IN
// PARALLEL (256 threads per pair, 2 elements per thread), argmax, install
// merged node, shift sequence. One block (512 threads) per sorted slot.
// ---------------------------------------------------------------------------
__global__ void __launch_bounds__(512)
k_step(int iter, const float* __restrict__ bcomp, const float* __restrict__ q) {
    int s = blockIdx.x;
    int t = threadIdx.x;
    int len = g_slen[s];
    int valid = len - iter - 1;
    if (valid < 1) return;             // finished batch: frozen

    __shared__ float red[2][8];
    int rn = g_recn[s];
    int ph = t >> 8;                   // which recompute pair
    int tt = t & 255;
    if (ph < rn) {
        int left  = g_rec[s][ph][0];
        int right = g_rec[s][ph][1];
        const float* pl = g_pl[s][left];
        const float* pr = g_pr[s][right];
        float part = 0.0f;
#pragma unroll
        for (int e = 0; e < 2; e++) {
            int k = tt + e * 256;
            float vi  = pl[k]        + pr[k]        + bcomp[k];
            float vfl = pl[k + 512]  + pr[k + 512]  + bcomp[k + 512];
            float vfr = pl[k + 1024] + pr[k + 1024] + bcomp[k + 1024];
            float vu  = pl[k + 1536] + pr[k + 1536] + bcomp[k + 1536];
            float vo  = pl[k + 2048] + pr[k + 2048] + bcomp[k + 2048];
            float cl = g_c[s][left][k];
            float cr = g_c[s][right][k];
            float cc = cl * sigmoidf_(vfl + 1.0f) + cr * sigmoidf_(vfr + 1.0f)
                     + tanhf(vu) * sigmoidf_(vi);
            float hv = sigmoidf_(vo) * tanhf(cc);
            g_ch[s][left][k] = hv;
            g_cc[s][left][k] = cc;
            part += q[k] * hv;
        }
#pragma unroll
        for (int o = 16; o > 0; o >>= 1)
            part += __shfl_down_sync(0xffffffffu, part, o);
        if ((tt & 31) == 0) red[ph][tt >> 5] = part;
    }
    __syncthreads();
    if (tt < 8 && ph < rn) {
        float v = red[ph][tt];
        v += __shfl_down_sync(0xffu, v, 4);
        v += __shfl_down_sync(0xffu, v, 2);
        v += __shfl_down_sync(0xffu, v, 1);
        if (tt == 0) g_lg[s][g_rec[s][ph][0]] = v * 0.04419417382415922f;
    }
    __syncthreads();

    // merge
    int n = LL - iter;
    __shared__ int seq[LL];
    __shared__ int sh_bm;
    if (t < n) seq[t] = g_seq[s][t];
    __syncthreads();
    if (t == 0) {
        float best = -3.4e38f;
        int bm = 0;
        for (int j = 0; j < valid; j++) {
            float lg = g_lg[s][seq[j]];
            if (lg > best) { best = lg; bm = j; }
        }
        sh_bm = bm;
        int newid = LL + iter;
        int c = 0;
        if (bm > 0)              { g_rec[s][c][0] = seq[bm - 1]; g_rec[s][c][1] = newid;       c++; }
        if (bm + 2 < len - iter) { g_rec[s][c][0] = newid;       g_rec[s][c][1] = seq[bm + 2]; c++; }
        g_recn[s] = c;
        g_new[s] = newid;
    }
    __syncthreads();
    int bm = sh_bm;
    int leftid = seq[bm];
    int newid = LL + iter;
    g_h[s][newid][t] = g_ch[s][leftid][t];
    g_c[s][newid][t] = g_cc[s][leftid][t];
    if (t < n - 1)
        g_seq[s][t] = (t < bm) ? seq[t] : ((t == bm) ? newid : seq[t + 1]);
}

// ---------------------------------------------------------------------------
// Gather root h back to original batch order.
// ---------------------------------------------------------------------------
__global__ void __launch_bounds__(512)
k_out(float* __restrict__ out) {
    int s = blockIdx.x, k = threadIdx.x;
    out[(long)g_perm[s] * HH + k] = g_h[s][g_seq[s][0]][k];
}

// ---------------------------------------------------------------------------
extern "C" void kernel_launch(void* const* d_in, const int* in_sizes, int n_in,
                              void* d_out, int out_size) {
    (void)in_sizes; (void)n_in; (void)out_size;
    const float* x     = (const float*)d_in[0];
    const int*   len   = (const int*)  d_in[1];
    const float* Wword = (const float*)d_in[2];
    const float* bword = (const float*)d_in[3];
    const float* Wcomp = (const float*)d_in[4];
    const float* bcomp = (const float*)d_in[5];
    const float* q     = (const float*)d_in[6];
    float* out = (float*)d_out;

    k_sort<<<1, 256>>>(len);

    // word embedding: hc = x @ W_word^T + b_word (compacted rows)
    k_gemm_big<<<dim3(1024 / 128, 64), 256>>>(0, x, Wword, bword);
    // leaf projections through W_comp halves (compacted rows)
    k_gemm_big<<<dim3(5120 / 128, 64), 256>>>(1, x, Wcomp, bword);

    k_cand<<<dim3(LL - 1, BB), 512>>>(bcomp, q);
    k_merge0<<<BB, 512>>>();
    k_gemm_nodes<<<dim3(80, 4), 128>>>(0, Wcomp);

    for (int it = 1; it < LL - 1; ++it) {
        k_step<<<BB, 512>>>(it, bcomp, q);
        if (it < LL - 2)
            k_gemm_nodes<<<dim3(80, 4), 128>>>(it, Wcomp);
    }

    k_out<<<BB, 512>>>(out);
}

// round 10
// speedup vs baseline: 1.1729x; 1.1729x over previous
#include <cuda_runtime.h>
#include <math.h>

// Problem constants
#define BB 256    // batch
#define LL 32     // seq len
#define DD 512    // input dim
#define HH 512    // hidden
#define NN 63     // max nodes per batch
#define PP 2560   // 5*H projection width

// ---------------------------------------------------------------------------
// Persistent device state (deterministically rewritten each replay; stale
// values are provably never consulted for the output).
// ---------------------------------------------------------------------------
__device__ float g_h [BB][NN][HH];
__device__ float g_c [BB][NN][HH];
__device__ float g_pl[BB][NN][PP];
__device__ float g_pr[BB][NN][PP];
__device__ float g_ch[BB][NN][HH];
__device__ float g_cc[BB][NN][HH];
__device__ float g_lg[BB][NN];
__device__ int   g_seq[BB][LL];
__device__ int   g_new[BB];
__device__ int   g_rec[BB][2][2];
__device__ int   g_recn[BB];
__device__ int   g_perm[BB];
__device__ int   g_slen[BB];
__device__ int   g_cntge[34];
__device__ int   g_off[33];
__device__ int   g_nrows;
__device__ int   g_rowmap[BB * LL];

__device__ __forceinline__ float sigmoidf_(float x) {
    return 1.0f / (1.0f + expf(-x));
}

// ---------------------------------------------------------------------------
// Sort batches by length descending (stable) + prefix counts + compacted
// (leaf,slot) row list. One block.
// ---------------------------------------------------------------------------
__global__ void k_sort(const int* __restrict__ length) {
    int tid = threadIdx.x;
    if (tid == 0) {
        int cnt[33];
        for (int v = 0; v < 33; v++) cnt[v] = 0;
        for (int b = 0; b < BB; b++) cnt[length[b]]++;
        int pos[33];
        int acc = 0;
        for (int v = 32; v >= 0; v--) { pos[v] = acc; acc += cnt[v]; }
        for (int b = 0; b < BB; b++) {
            int v = length[b];
            int sl = pos[v]++;
            g_perm[sl] = b;
            g_slen[sl] = v;
        }
        for (int t = 0; t < 34; t++) {
            int c = 0;
            for (int v = t; v < 33; v++) c += cnt[v];
            g_cntge[t] = c;
        }
        int off = 0;
        for (int l = 0; l < 32; l++) { g_off[l] = off; off += g_cntge[l + 1]; }
        g_off[32] = off;
        g_nrows = off;
    }
    __syncthreads();
    for (int l = 0; l < 32; l++)
        if (tid < g_cntge[l + 1])
            g_rowmap[g_off[l] + tid] = (l << 8) | tid;
}

// ---------------------------------------------------------------------------
// Big fp32 GEMM over COMPACTED rows: 128x128 tile, BK=8, 256 threads, 8x8.
// (unchanged — measured ~45 TF/s)
// ---------------------------------------------------------------------------
__global__ void __launch_bounds__(256)
k_gemm_big(int mode, const float* __restrict__ X, const float* __restrict__ W,
           const float* __restrict__ bias) {
    __shared__ float As[8][132];
    __shared__ float Bs[8][132];
    int bm = blockIdx.y * 128;
    int nrows = g_nrows;
    if (bm >= nrows) return;
    int bn = blockIdx.x * 128;

    int tid = threadIdx.x;
    int lr = tid >> 1;          // 0..127 load row
    int lc = (tid & 1) << 2;    // 0 or 4

    int r = bm + lr;
    int rm = g_rowmap[(r < nrows) ? r : bm];
    int l = rm >> 8, s = rm & 255;
    const float* arow;
    if (mode == 0) arow = X + ((long)g_perm[s] * LL + l) * DD + lc;
    else           arow = &g_h[s][l][lc];

    int nrow = bn + lr;
    const float* brow;
    if (mode == 0) brow = W + (long)nrow * DD + lc;
    else brow = (nrow < PP) ? (W + (long)nrow * (2 * HH) + lc)
                            : (W + (long)(nrow - PP) * (2 * HH) + HH + lc);

    int tx = tid & 15, ty = tid >> 4;
    float acc[8][8];
#pragma unroll
    for (int i = 0; i < 8; i++)
#pragma unroll
        for (int j = 0; j < 8; j++) acc[i][j] = 0.0f;

    for (int k0 = 0; k0 < DD; k0 += 8) {
        float4 a = *(const float4*)(arow + k0);
        float4 b = *(const float4*)(brow + k0);
        As[lc + 0][lr] = a.x; As[lc + 1][lr] = a.y;
        As[lc + 2][lr] = a.z; As[lc + 3][lr] = a.w;
        Bs[lc + 0][lr] = b.x; Bs[lc + 1][lr] = b.y;
        Bs[lc + 2][lr] = b.z; Bs[lc + 3][lr] = b.w;
        __syncthreads();
#pragma unroll
        for (int k = 0; k < 8; k++) {
            float av[8], bv[8];
            float4 t0 = *(const float4*)&As[k][ty * 4];
            float4 t1 = *(const float4*)&As[k][64 + ty * 4];
            av[0]=t0.x; av[1]=t0.y; av[2]=t0.z; av[3]=t0.w;
            av[4]=t1.x; av[5]=t1.y; av[6]=t1.z; av[7]=t1.w;
            float4 u0 = *(const float4*)&Bs[k][tx * 4];
            float4 u1 = *(const float4*)&Bs[k][64 + tx * 4];
            bv[0]=u0.x; bv[1]=u0.y; bv[2]=u0.z; bv[3]=u0.w;
            bv[4]=u1.x; bv[5]=u1.y; bv[6]=u1.z; bv[7]=u1.w;
#pragma unroll
            for (int i = 0; i < 8; i++)
#pragma unroll
                for (int j = 0; j < 8; j++)
                    acc[i][j] = fmaf(av[i], bv[j], acc[i][j]);
        }
        __syncthreads();
    }

#pragma unroll
    for (int i = 0; i < 8; i++) {
        int mi = (i < 4) ? (ty * 4 + i) : (64 + ty * 4 + (i - 4));
        int r2 = bm + mi;
        if (r2 >= nrows) continue;
        int rm2 = g_rowmap[r2];
        int l2 = rm2 >> 8, s2 = rm2 & 255;
#pragma unroll
        for (int j = 0; j < 8; j++) {
            int nj = (j < 4) ? (tx * 4 + j) : (64 + tx * 4 + (j - 4));
            int n = bn + nj;
            float v = acc[i][j];
            if (mode == 0) {
                v += bias[n];
                if (n < HH) g_h[s2][l2][n] = v;
                else        g_c[s2][l2][n - HH] = v;
            } else {
                if (n < PP) g_pl[s2][l2][n] = v;
                else        g_pr[s2][l2][n - PP] = v;
            }
        }
    }
}

// ---------------------------------------------------------------------------
// Per-iteration node-projection GEMM v4: 64x64 tile, 128 threads (4 warps),
// 4x8 microtile, BK=16, register prefetch, BANK-CONFLICT-FREE padded B
// layout: column n stored at n + ((n>>5)<<2) (row width 68). B reads then
// span all 32 banks; A reads are 4-line broadcasts. fma-bound by design.
// Grid (80, 4) = 320 CTAs; rows needing projection: s < cntge[iter+3].
// Per-output accumulation order unchanged -> bit-identical results.
// ---------------------------------------------------------------------------
__global__ void __launch_bounds__(128)
k_gemm_nodes(int iter, const float* __restrict__ W) {
    __shared__ float As[16][68];
    __shared__ float Bs[16][68];
    int act = g_cntge[iter + 3];
    int bm = blockIdx.y * 64;
    if (bm >= act) return;
    int bn = blockIdx.x * 64;
    int t = threadIdx.x;

    // loaders: 64 rows x 16 K; 128 threads x 2 float4 each side.
    int lr = t & 63;            // row 0..63
    int lc = (t >> 6) << 3;     // K offset 0 or 8
    int plr = lr + ((lr >> 5) << 2);   // padded column for B stores

    int s = bm + lr;
    int sc = (s < act) ? s : bm;
    const float* arow = &g_h[sc][g_new[sc]][lc];
    int nrow = bn + lr;
    const float* brow = ((nrow < PP) ? (W + (long)nrow * (2 * HH))
                                     : (W + (long)(nrow - PP) * (2 * HH) + HH)) + lc;

    int tx = t & 7, ty = t >> 3;   // tx: 8 N-groups of 8; ty: 16 M-groups of 4
    // padded read offsets for B (4-aligned, never cross the 32-col boundary)
    int c0 = tx * 8;      c0 += (c0 >> 5) << 2;
    int c1 = tx * 8 + 4;  c1 += (c1 >> 5) << 2;

    float acc[4][8];
#pragma unroll
    for (int i = 0; i < 4; i++)
#pragma unroll
        for (int j = 0; j < 8; j++) acc[i][j] = 0.0f;

    float4 pa0 = *(const float4*)arow;
    float4 pa1 = *(const float4*)(arow + 4);
    float4 pb0 = *(const float4*)brow;
    float4 pb1 = *(const float4*)(brow + 4);

    for (int k0 = 0; k0 < DD; k0 += 16) {
        As[lc + 0][lr] = pa0.x; As[lc + 1][lr] = pa0.y;
        As[lc + 2][lr] = pa0.z; As[lc + 3][lr] = pa0.w;
        As[lc + 4][lr] = pa1.x; As[lc + 5][lr] = pa1.y;
        As[lc + 6][lr] = pa1.z; As[lc + 7][lr] = pa1.w;
        Bs[lc + 0][plr] = pb0.x; Bs[lc + 1][plr] = pb0.y;
        Bs[lc + 2][plr] = pb0.z; Bs[lc + 3][plr] = pb0.w;
        Bs[lc + 4][plr] = pb1.x; Bs[lc + 5][plr] = pb1.y;
        Bs[lc + 6][plr] = pb1.z; Bs[lc + 7][plr] = pb1.w;
        __syncthreads();
        if (k0 + 16 < DD) {
            pa0 = *(const float4*)(arow + k0 + 16);
            pa1 = *(const float4*)(arow + k0 + 20);
            pb0 = *(const float4*)(brow + k0 + 16);
            pb1 = *(const float4*)(brow + k0 + 20);
        }
#pragma unroll
        for (int k = 0; k < 16; k++) {
            float4 av = *(const float4*)&As[k][ty * 4];   // 4-line broadcast
            float4 b0 = *(const float4*)&Bs[k][c0];       // all-32-bank spread
            float4 b1 = *(const float4*)&Bs[k][c1];
            float ar[4] = {av.x, av.y, av.z, av.w};
            float br[8] = {b0.x, b0.y, b0.z, b0.w, b1.x, b1.y, b1.z, b1.w};
#pragma unroll
            for (int i = 0; i < 4; i++)
#pragma unroll
                for (int j = 0; j < 8; j++)
                    acc[i][j] = fmaf(ar[i], br[j], acc[i][j]);
        }
        __syncthreads();
    }

    // Whole 64-wide N-tile is uniformly pl or pr (PP % 64 == 0).
    int nb = bn + tx * 8;
#pragma unroll
    for (int i = 0; i < 4; i++) {
        int ss = bm + ty * 4 + i;
        if (ss >= act) continue;
        int node = g_new[ss];
        float* dst = (bn < PP) ? &g_pl[ss][node][nb] : &g_pr[ss][node][nb - PP];
        *(float4*)dst       = make_float4(acc[i][0], acc[i][1], acc[i][2], acc[i][3]);
        *(float4*)(dst + 4) = make_float4(acc[i][4], acc[i][5], acc[i][6], acc[i][7]);
    }
}

// ---------------------------------------------------------------------------
// Iteration-0 candidate compose for all initial pairs. Grid (31, 256).
// ---------------------------------------------------------------------------
__global__ void __launch_bounds__(512)
k_cand(const float* __restrict__ bcomp, const float* __restrict__ q) {
    int s = blockIdx.y;
    int slot = blockIdx.x;
    if (slot >= g_slen[s] - 1) return;
    int left = slot, right = slot + 1;
    int k = threadIdx.x;
    const float* pl = g_pl[s][left];
    const float* pr = g_pr[s][right];
    float vi  = pl[k]        + pr[k]        + bcomp[k];
    float vfl = pl[k + 512]  + pr[k + 512]  + bcomp[k + 512];
    float vfr = pl[k + 1024] + pr[k + 1024] + bcomp[k + 1024];
    float vu  = pl[k + 1536] + pr[k + 1536] + bcomp[k + 1536];
    float vo  = pl[k + 2048] + pr[k + 2048] + bcomp[k + 2048];
    float cl = g_c[s][left][k];
    float cr = g_c[s][right][k];
    float cc = cl * sigmoidf_(vfl + 1.0f) + cr * sigmoidf_(vfr + 1.0f)
             + tanhf(vu) * sigmoidf_(vi);
    float hh = sigmoidf_(vo) * tanhf(cc);
    g_ch[s][left][k] = hh;
    g_cc[s][left][k] = cc;

    float part = q[k] * hh;
#pragma unroll
    for (int o = 16; o > 0; o >>= 1)
        part += __shfl_down_sync(0xffffffffu, part, o);
    __shared__ float red[16];
    if ((k & 31) == 0) red[k >> 5] = part;
    __syncthreads();
    if (k < 16) {
        float v = red[k];
#pragma unroll
        for (int o = 8; o > 0; o >>= 1)
            v += __shfl_down_sync(0xffffu, v, o);
        if (k == 0) g_lg[s][left] = v * 0.04419417382415922f;  // 1/sqrt(512)
    }
}

// ---------------------------------------------------------------------------
// Iteration-0 merge (argmax + install + shift). One block per slot.
// ---------------------------------------------------------------------------
__global__ void __launch_bounds__(512)
k_merge0() {
    int s = blockIdx.x;
    int t = threadIdx.x;
    int len = g_slen[s];
    int valid = len - 1;
    __shared__ int seq[LL];
    __shared__ int sh_bm;
    if (t < LL) seq[t] = t;
    __syncthreads();
    if (t == 0) {
        float best = -3.4e38f;
        int bm = 0;
        for (int j = 0; j < valid; j++) {
            float lg = g_lg[s][seq[j]];
            if (lg > best) { best = lg; bm = j; }
        }
        sh_bm = bm;
        int newid = LL;
        int c = 0;
        if (bm > 0)       { g_rec[s][c][0] = seq[bm - 1]; g_rec[s][c][1] = newid;       c++; }
        if (bm + 2 < len) { g_rec[s][c][0] = newid;       g_rec[s][c][1] = seq[bm + 2]; c++; }
        g_recn[s] = c;
        g_new[s] = newid;
    }
    __syncthreads();
    int bm = sh_bm;
    int leftid = seq[bm];
    int newid = LL;
    g_h[s][newid][t] = g_ch[s][leftid][t];
    g_c[s][newid][t] = g_cc[s][leftid][t];
    if (t < LL - 1)
        g_seq[s][t] = (t < bm) ? seq[t] : ((t == bm) ? newid : seq[t + 1]);
}

// ---------------------------------------------------------------------------
// Fused per-iteration step (iter >= 1): recompute <=2 candidate pairs,
// argmax over valid pairs, install merged node, shift sequence.
// (R8 serial-pair version — known good)
// ---------------------------------------------------------------------------
__global__ void __launch_bounds__(512)
k_step(int iter, const float* __restrict__ bcomp, const float* __restrict__ q) {
    int s = blockIdx.x;
    int t = threadIdx.x;
    int len = g_slen[s];
    int valid = len - iter - 1;
    if (valid < 1) return;             // finished batch: frozen

    __shared__ float red[16];
    int rn = g_recn[s];
    for (int p = 0; p < rn; p++) {
        int left  = g_rec[s][p][0];
        int right = g_rec[s][p][1];
        const float* pl = g_pl[s][left];
        const float* pr = g_pr[s][right];
        float vi  = pl[t]        + pr[t]        + bcomp[t];
        float vfl = pl[t + 512]  + pr[t + 512]  + bcomp[t + 512];
        float vfr = pl[t + 1024] + pr[t + 1024] + bcomp[t + 1024];
        float vu  = pl[t + 1536] + pr[t + 1536] + bcomp[t + 1536];
        float vo  = pl[t + 2048] + pr[t + 2048] + bcomp[t + 2048];
        float cl = g_c[s][left][t];
        float cr = g_c[s][right][t];
        float cc = cl * sigmoidf_(vfl + 1.0f) + cr * sigmoidf_(vfr + 1.0f)
                 + tanhf(vu) * sigmoidf_(vi);
        float hh = sigmoidf_(vo) * tanhf(cc);
        g_ch[s][left][t] = hh;
        g_cc[s][left][t] = cc;

        float part = q[t] * hh;
#pragma unroll
        for (int o = 16; o > 0; o >>= 1)
            part += __shfl_down_sync(0xffffffffu, part, o);
        if ((t & 31) == 0) red[t >> 5] = part;
        __syncthreads();
        if (t < 16) {
            float v = red[t];
#pragma unroll
            for (int o = 8; o > 0; o >>= 1)
                v += __shfl_down_sync(0xffffu, v, o);
            if (t == 0) g_lg[s][left] = v * 0.04419417382415922f;
        }
        __syncthreads();
    }

    int n = LL - iter;
    __shared__ int seq[LL];
    __shared__ int sh_bm;
    if (t < n) seq[t] = g_seq[s][t];
    __syncthreads();
    if (t == 0) {
        float best = -3.4e38f;
        int bm = 0;
        for (int j = 0; j < valid; j++) {
            float lg = g_lg[s][seq[j]];
            if (lg > best) { best = lg; bm = j; }
        }
        sh_bm = bm;
        int newid = LL + iter;
        int c = 0;
        if (bm > 0)              { g_rec[s][c][0] = seq[bm - 1]; g_rec[s][c][1] = newid;       c++; }
        if (bm + 2 < len - iter) { g_rec[s][c][0] = newid;       g_rec[s][c][1] = seq[bm + 2]; c++; }
        g_recn[s] = c;
        g_new[s] = newid;
    }
    __syncthreads();
    int bm = sh_bm;
    int leftid = seq[bm];
    int newid = LL + iter;
    g_h[s][newid][t] = g_ch[s][leftid][t];
    g_c[s][newid][t] = g_cc[s][leftid][t];
    if (t < n - 1)
        g_seq[s][t] = (t < bm) ? seq[t] : ((t == bm) ? newid : seq[t + 1]);
}

// ---------------------------------------------------------------------------
// Gather root h back to original batch order.
// ---------------------------------------------------------------------------
__global__ void __launch_bounds__(512)
k_out(float* __restrict__ out) {
    int s = blockIdx.x, k = threadIdx.x;
    out[(long)g_perm[s] * HH + k] = g_h[s][g_seq[s][0]][k];
}

// ---------------------------------------------------------------------------
extern "C" void kernel_launch(void* const* d_in, const int* in_sizes, int n_in,
                              void* d_out, int out_size) {
    (void)in_sizes; (void)n_in; (void)out_size;
    const float* x     = (const float*)d_in[0];
    const int*   len   = (const int*)  d_in[1];
    const float* Wword = (const float*)d_in[2];
    const float* bword = (const float*)d_in[3];
    const float* Wcomp = (const float*)d_in[4];
    const float* bcomp = (const float*)d_in[5];
    const float* q     = (const float*)d_in[6];
    float* out = (float*)d_out;

    k_sort<<<1, 256>>>(len);

    // word embedding: hc = x @ W_word^T + b_word (compacted rows)
    k_gemm_big<<<dim3(1024 / 128, 64), 256>>>(0, x, Wword, bword);
    // leaf projections through W_comp halves (compacted rows)
    k_gemm_big<<<dim3(5120 / 128, 64), 256>>>(1, x, Wcomp, bword);

    k_cand<<<dim3(LL - 1, BB), 512>>>(bcomp, q);
    k_merge0<<<BB, 512>>>();
    k_gemm_nodes<<<dim3(80, 4), 128>>>(0, Wcomp);

    for (int it = 1; it < LL - 1; ++it) {
        k_step<<<BB, 512>>>(it, bcomp, q);
        if (it < LL - 2)
            k_gemm_nodes<<<dim3(80, 4), 128>>>(it, Wcomp);
    }

    k_out<<<BB, 512>>>(out);
}